// round 8
// baseline (speedup 1.0000x reference)
#include <cuda.h>
#include <cuda_runtime.h>
#include <cuda_fp16.h>
#include <cstdint>

// ============================================================================
// out = elu( (adj>0 ? (input@W)/cnt_row : 0) ), cnt_row = #(adj>0 in row);
// cnt==0 rows: softmax of all-(-9e15) is uniform 1/256.
// R8: R7 (2 CTAs/SM) still exposed 2 syncs/iter (issue 21%, L1 67%). Now ONE
//     sync/iter: single A32 stage + A16 double buffer, convert(i+1) overlaps
//     MMA(i). Smem 100KB keeps 2 CTAs/SM.
// ============================================================================

#define N_ROWS 200000
#define K_DIM  512
#define M_DIM  256
#define BM     64
#define BK     64
#define NITER  (K_DIM / BK)     // 8
#define THREADS 256             // 8 warps: 2 (m) x 4 (n), warp tile 32x64

// --- shared memory layout (bytes) --------------------------------------------
// MBAR_A @0, MBAR_B0 @8, MBAR_B1 @16; MASK @128 (u32[64][8] -> 2176);
// CNT @2176 (int[64][4] -> 3200); A16 @4096 (2 x 8KB -> 20480);
// A32 @20480 (16KB, two 8KB subtiles fp32 [64][32] SW128 -> 36864);
// B @36864 (2 x 32KB fp16 [256][64] SW128 -> 102400). Total 100KB -> 2 CTAs/SM.
#define MBAR_A     0
#define MBAR_B(s)  (8 + (s) * 8)
#define MASK_OFF   128
#define CNT_OFF    (MASK_OFF + 64 * 8 * 4)      // 2176
#define A16_OFF    4096
#define A32_OFF    20480
#define B_OFF(s)   (36864 + (s) * 32768)
#define SMEM_TOTAL 102400
#define TXA        16384
#define TXB        32768

// --- device scratch: W transposed to [M][K], fp16 RN --------------------------
__device__ __half g_Wh[M_DIM * K_DIM];

// ============================================================================
// helpers (plain sm_90-level PTX; no 'a' features)
// ============================================================================
__device__ __forceinline__ uint32_t smem_u32(const void* p) {
    uint32_t a;
    asm("{ .reg .u64 t; cvta.to.shared.u64 t, %1; cvt.u32.u64 %0, t; }"
        : "=r"(a) : "l"(p));
    return a;
}
#define MBARRIER_INIT(mbar, count) \
    asm volatile("mbarrier.init.shared.b64 [%0], %1;" \
        :: "r"((uint32_t)(mbar)), "r"((uint32_t)(count)) : "memory")
#define MBARRIER_EXPECT_TX(mbar, bytes) \
    asm volatile("mbarrier.arrive.expect_tx.shared.b64 _, [%0], %1;" \
        :: "r"((uint32_t)(mbar)), "r"((uint32_t)(bytes)) : "memory")
#define MBARRIER_WAIT_PARITY(mbar, parity) do { \
    uint32_t _mbar = (uint32_t)(mbar); \
    uint32_t _par = (uint32_t)(parity); \
    uint32_t _done; \
    asm volatile( \
        "{\n\t.reg .pred p;\n\t" \
        "mbarrier.try_wait.parity.acquire.cta.shared::cta.b64 p, [%1], %2;\n\t" \
        "selp.b32 %0, 1, 0, p;\n\t}" \
        : "=r"(_done) : "r"(_mbar), "r"(_par) : "memory"); \
    if (!_done) { \
        asm volatile( \
            "{\n\t.reg .pred P1;\n\t" \
            "WAIT_LOOP_%=:\n\t" \
            "mbarrier.try_wait.parity.acquire.cta.shared::cta.b64 P1, [%0], %1, 0x989680;\n\t" \
            "@P1 bra.uni WAIT_DONE_%=;\n\t" \
            "bra.uni WAIT_LOOP_%=;\n\t" \
            "WAIT_DONE_%=:\n\t}" \
            :: "r"(_mbar), "r"(_par) : "memory"); \
    } \
} while (0)
#define TMA_LOAD_2D(smem_addr, map_ptr, cx, cy, mbar) \
    asm volatile( \
        "cp.async.bulk.tensor.2d.shared::cta.global.tile.mbarrier::complete_tx::bytes " \
        "[%0], [%1, {%2, %3}], [%4];" \
        :: "r"((uint32_t)(smem_addr)), "l"(map_ptr), \
           "r"((int32_t)(cx)), "r"((int32_t)(cy)), "r"((uint32_t)(mbar)) \
        : "memory")

__device__ __forceinline__ float4 lds128f(uint32_t a) {
    float4 v;
    asm volatile("ld.shared.v4.f32 {%0,%1,%2,%3}, [%4];"
                 : "=f"(v.x), "=f"(v.y), "=f"(v.z), "=f"(v.w) : "r"(a));
    return v;
}
__device__ __forceinline__ void sts128(uint32_t a, uint32_t r0, uint32_t r1,
                                       uint32_t r2, uint32_t r3) {
    asm volatile("st.shared.v4.b32 [%0], {%1,%2,%3,%4};"
                 :: "r"(a), "r"(r0), "r"(r1), "r"(r2), "r"(r3) : "memory");
}
__device__ __forceinline__ void ldsm_x4(uint32_t* r, uint32_t addr) {
    asm volatile("ldmatrix.sync.aligned.m8n8.x4.shared.b16 {%0,%1,%2,%3}, [%4];"
                 : "=r"(r[0]), "=r"(r[1]), "=r"(r[2]), "=r"(r[3]) : "r"(addr));
}
__device__ __forceinline__ uint32_t packh2(float lo, float hi) {
    uint32_t d;
    asm("cvt.rn.f16x2.f32 %0, %1, %2;" : "=r"(d) : "f"(hi), "f"(lo));
    return d;
}
__device__ __forceinline__ void mma16816(float* c, const uint32_t* a,
                                         const uint32_t* b) {
    asm volatile(
        "mma.sync.aligned.m16n8k16.row.col.f32.f16.f16.f32 "
        "{%0,%1,%2,%3}, {%4,%5,%6,%7}, {%8,%9}, {%0,%1,%2,%3};"
        : "+f"(c[0]), "+f"(c[1]), "+f"(c[2]), "+f"(c[3])
        : "r"(a[0]), "r"(a[1]), "r"(a[2]), "r"(a[3]), "r"(b[0]), "r"(b[1]));
}

// ============================================================================
// prep: W [K=512, M=256] row-major fp32 -> g_Wh [M][K] fp16 (RN)
// ============================================================================
__global__ void prep_wh_kernel(const float* __restrict__ W) {
    int idx = blockIdx.x * blockDim.x + threadIdx.x;
    int k = idx >> 8;
    int m = idx & 255;
    g_Wh[m * K_DIM + k] = __float2half_rn(W[idx]);
}

// ============================================================================
// fused GEMM (TMA + overlapped smem-convert + ldmatrix + mma.sync) + attention
// ============================================================================
__global__ void __launch_bounds__(THREADS, 2) gat_kernel(
    const __grid_constant__ CUtensorMap tmap_a,
    const __grid_constant__ CUtensorMap tmap_b,
    const int* __restrict__ adj,
    float* __restrict__ out)
{
    extern __shared__ char smem[];
    const uint32_t sb = smem_u32(smem);
    uint32_t* smask = (uint32_t*)(smem + MASK_OFF);   // [64][8]
    int* scnt = (int*)(smem + CNT_OFF);               // [64][4]

    const int tid  = threadIdx.x;
    const int lane = tid & 31;
    const int wid  = tid >> 5;
    const int wm   = wid >> 2;   // 0..1 : 32-row band
    const int wn   = wid & 3;    // 0..3 : 64-col band
    const int tile = blockIdx.x * BM;

    // ---- mbarrier init + TMA prologue -----------------------------------------
    if (tid == 0) {
        MBARRIER_INIT(sb + MBAR_A, 1);
        MBARRIER_INIT(sb + MBAR_B(0), 1);
        MBARRIER_INIT(sb + MBAR_B(1), 1);
    }
    __syncthreads();
    if (tid == 0) {
        MBARRIER_EXPECT_TX(sb + MBAR_A, TXA);
        TMA_LOAD_2D(sb + A32_OFF,        &tmap_a, 0,  tile, sb + MBAR_A);
        TMA_LOAD_2D(sb + A32_OFF + 8192, &tmap_a, 32, tile, sb + MBAR_A);
        MBARRIER_EXPECT_TX(sb + MBAR_B(0), TXB);
        TMA_LOAD_2D(sb + B_OFF(0), &tmap_b, 0,  0, sb + MBAR_B(0));
        MBARRIER_EXPECT_TX(sb + MBAR_B(1), TXB);
        TMA_LOAD_2D(sb + B_OFF(1), &tmap_b, BK, 0, sb + MBAR_B(1));
    }

    // ---- adj mask + count (overlaps TMA flight; 64 | N_ROWS, no clamps) --------
    {
        int r = tid >> 2;            // 0..63
        int q = tid & 3;             // 64-col quarter
        const int4* ap = (const int4*)(adj + (size_t)(tile + r) * M_DIM + q * 64);
        int cnt = 0;
        #pragma unroll
        for (int g = 0; g < 2; g++) {
            uint32_t m = 0;
            #pragma unroll
            for (int w = 0; w < 8; w++) {
                int4 v = __ldg(ap + g * 8 + w);
                m |= (v.x > 0 ? 1u : 0u) << (w * 4 + 0);
                m |= (v.y > 0 ? 1u : 0u) << (w * 4 + 1);
                m |= (v.z > 0 ? 1u : 0u) << (w * 4 + 2);
                m |= (v.w > 0 ? 1u : 0u) << (w * 4 + 3);
            }
            smask[r * 8 + q * 2 + g] = m;
            cnt += __popc(m);
        }
        scnt[r * 4 + q] = cnt;
    }

    // ---- per-thread constants ----------------------------------------------------
    const int arow = lane >> 2;                 // 0..7

    // convert mapping: row cr = tid>>2 (0..63), k-quarter cq = tid&3
    const int cr = tid >> 2;
    const int cq = tid & 3;
    const uint32_t crx = (uint32_t)(cr & 7) << 4;
    const uint32_t csrc = sb + A32_OFF + (uint32_t)(cq >> 1) * 8192 + (uint32_t)cr * 128;
    const uint32_t cu0 = (uint32_t)(cq & 1) * 4;
    const uint32_t cdst_base = sb + A16_OFF + (uint32_t)cr * 128;

    // ldmatrix lane addressing (SW128 XOR on 128B rows)
    const uint32_t l7 = lane & 7;
    const uint32_t lxor = l7 << 4;
    const uint32_t a_row = (uint32_t)(wm * 32) + l7 + ((lane >> 3) & 1) * 8;
    const uint32_t a_kseg = ((lane >> 4) & 1) * 16;
    const uint32_t a_base0 = sb + A16_OFF + a_row * 128;
    const uint32_t b_row = (uint32_t)(wn * 64) + l7 + ((lane >> 4) & 1) * 8;
    const uint32_t b_kseg = ((lane >> 3) & 1) * 16;
    const uint32_t b_base_off = b_row * 128;

    float c[2][8][4];
    #pragma unroll
    for (int mf = 0; mf < 2; mf++)
        #pragma unroll
        for (int nf = 0; nf < 8; nf++)
            #pragma unroll
            for (int e = 0; e < 4; e++) c[mf][nf][e] = 0.0f;

    // ---- prologue convert: chunk 0 -> A16 buf 0 ----------------------------------
    MBARRIER_WAIT_PARITY(sb + MBAR_A, 0);
    {
        float4 f0 = lds128f(csrc + (((cu0 + 0) << 4) ^ crx));
        float4 f1 = lds128f(csrc + (((cu0 + 1) << 4) ^ crx));
        float4 f2 = lds128f(csrc + (((cu0 + 2) << 4) ^ crx));
        float4 f3 = lds128f(csrc + (((cu0 + 3) << 4) ^ crx));
        sts128(cdst_base + (((uint32_t)(cq * 2 + 0) << 4) ^ crx),
               packh2(f0.x, f0.y), packh2(f0.z, f0.w),
               packh2(f1.x, f1.y), packh2(f1.z, f1.w));
        sts128(cdst_base + (((uint32_t)(cq * 2 + 1) << 4) ^ crx),
               packh2(f2.x, f2.y), packh2(f2.z, f2.w),
               packh2(f3.x, f3.y), packh2(f3.z, f3.w));
    }
    __syncthreads();            // convert(0) done; A32 free
    if (tid == 0) {             // issue TMA A(1)
        MBARRIER_EXPECT_TX(sb + MBAR_A, TXA);
        TMA_LOAD_2D(sb + A32_OFF,        &tmap_a, BK,      tile, sb + MBAR_A);
        TMA_LOAD_2D(sb + A32_OFF + 8192, &tmap_a, BK + 32, tile, sb + MBAR_A);
    }

    // ---- mainloop: 8 x BK=64, ONE sync per iter ------------------------------------
    #pragma unroll 1
    for (int i = 0; i < NITER; i++) {
        // (1) convert chunk i+1 into the other A16 buffer (overlaps MMA issue)
        if (i + 1 < NITER) {
            MBARRIER_WAIT_PARITY(sb + MBAR_A, (uint32_t)((i + 1) & 1));
            const uint32_t cdst = cdst_base + (uint32_t)((i + 1) & 1) * 8192;
            float4 f0 = lds128f(csrc + (((cu0 + 0) << 4) ^ crx));
            float4 f1 = lds128f(csrc + (((cu0 + 1) << 4) ^ crx));
            float4 f2 = lds128f(csrc + (((cu0 + 2) << 4) ^ crx));
            float4 f3 = lds128f(csrc + (((cu0 + 3) << 4) ^ crx));
            sts128(cdst + (((uint32_t)(cq * 2 + 0) << 4) ^ crx),
                   packh2(f0.x, f0.y), packh2(f0.z, f0.w),
                   packh2(f1.x, f1.y), packh2(f1.z, f1.w));
            sts128(cdst + (((uint32_t)(cq * 2 + 1) << 4) ^ crx),
                   packh2(f2.x, f2.y), packh2(f2.z, f2.w),
                   packh2(f3.x, f3.y), packh2(f3.z, f3.w));
        }

        // (2) MMAs on A16 buf i&1 + B slot i&1
        MBARRIER_WAIT_PARITY(sb + MBAR_B(i & 1), (uint32_t)((i >> 1) & 1));
        {
            const uint32_t aB = a_base0 + (uint32_t)(i & 1) * 8192;
            const uint32_t bB = sb + B_OFF(i & 1) + b_base_off;
            #pragma unroll
            for (int ks = 0; ks < 4; ks++) {
                const uint32_t ak = ((uint32_t)ks * 32 + a_kseg) ^ lxor;
                const uint32_t bk = ((uint32_t)ks * 32 + b_kseg) ^ lxor;
                uint32_t ra[2][4];
                ldsm_x4(ra[0], aB + ak);
                ldsm_x4(ra[1], aB + 2048 + ak);
                #pragma unroll
                for (int np = 0; np < 4; np++) {
                    uint32_t rb[4];
                    ldsm_x4(rb, bB + (uint32_t)np * 2048 + bk);
                    mma16816(c[0][np * 2 + 0], ra[0], rb);
                    mma16816(c[0][np * 2 + 1], ra[0], rb + 2);
                    mma16816(c[1][np * 2 + 0], ra[1], rb);
                    mma16816(c[1][np * 2 + 1], ra[1], rb + 2);
                }
            }
        }
        __syncthreads();   // retires: convert writes, A32 reads, B[i&1] reads, A16[i&1] reads

        // (3) refills for chunk i+2 (A32 and B slot i&1 both just freed)
        if (tid == 0 && i + 2 < NITER) {
            const int j = i + 2;
            MBARRIER_EXPECT_TX(sb + MBAR_A, TXA);
            TMA_LOAD_2D(sb + A32_OFF,        &tmap_a, j * BK,      tile, sb + MBAR_A);
            TMA_LOAD_2D(sb + A32_OFF + 8192, &tmap_a, j * BK + 32, tile, sb + MBAR_A);
            MBARRIER_EXPECT_TX(sb + MBAR_B(i & 1), TXB);
            TMA_LOAD_2D(sb + B_OFF(i & 1), &tmap_b, j * BK, 0, sb + MBAR_B(i & 1));
        }
    }

    // ---- epilogue: scale by 1/cnt on mask, elu, store -------------------------------
    #pragma unroll
    for (int mf = 0; mf < 2; mf++) {
        const int r0 = wm * 32 + mf * 16 + arow;
        #pragma unroll
        for (int half = 0; half < 2; half++) {
            const int rr = r0 + half * 8;
            const int grow = tile + rr;
            const int cnt = scnt[rr * 4] + scnt[rr * 4 + 1] +
                            scnt[rr * 4 + 2] + scnt[rr * 4 + 3];
            const bool all_on = (cnt == 0);
            const float scale = all_on ? (1.0f / 256.0f) : (1.0f / (float)cnt);
            #pragma unroll
            for (int nf = 0; nf < 8; nf++) {
                const int col = wn * 64 + nf * 8 + (int)(lane & 3) * 2;
                const uint32_t mw = smask[rr * 8 + (col >> 5)];
                float2 o;
                #pragma unroll
                for (int e = 0; e < 2; e++) {
                    float h = c[mf][nf][half * 2 + e];
                    bool on = all_on | (((mw >> ((col + e) & 31)) & 1u) != 0u);
                    float v = on ? h * scale : 0.0f;
                    float res = (v > 0.0f) ? v : (__expf(v) - 1.0f);
                    ((float*)&o)[e] = res;
                }
                *(float2*)(out + (size_t)grow * M_DIM + col) = o;
            }
        }
    }
}

// ============================================================================
// host launch
// ============================================================================
typedef CUresult (*EncodeTiledFn)(
    CUtensorMap*, CUtensorMapDataType, cuuint32_t, void*,
    const cuuint64_t*, const cuuint64_t*, const cuuint32_t*, const cuuint32_t*,
    CUtensorMapInterleave, CUtensorMapSwizzle, CUtensorMapL2promotion,
    CUtensorMapFloatOOBfill);

extern "C" void kernel_launch(void* const* d_in, const int* in_sizes, int n_in,
                              void* d_out, int out_size) {
    const float* inp = (const float*)d_in[0];
    const int*   adj = (const int*)d_in[1];
    const float* W   = (const float*)d_in[2];
    // d_in[3] ('a') provably cancels in the softmax; unused.
    float* out = (float*)d_out;

    prep_wh_kernel<<<(K_DIM * M_DIM) / 256, 256>>>(W);

    void* wh_ptr = nullptr;
    cudaGetSymbolAddress(&wh_ptr, g_Wh);

    void* fp = nullptr;
    cudaDriverEntryPointQueryResult qres;
    cudaGetDriverEntryPointByVersion("cuTensorMapEncodeTiled", &fp, 12000,
                                     cudaEnableDefault, &qres);
    EncodeTiledFn enc = (EncodeTiledFn)fp;

    alignas(64) CUtensorMap tmA;
    alignas(64) CUtensorMap tmB;
    {
        cuuint64_t dims[2]    = {(cuuint64_t)K_DIM, (cuuint64_t)N_ROWS};
        cuuint64_t strides[1] = {(cuuint64_t)K_DIM * sizeof(float)};
        cuuint32_t box[2]     = {32u, (cuuint32_t)BM};      // 128B x 64 rows
        cuuint32_t es[2]      = {1, 1};
        enc(&tmA, CU_TENSOR_MAP_DATA_TYPE_FLOAT32, 2, (void*)inp,
            dims, strides, box, es,
            CU_TENSOR_MAP_INTERLEAVE_NONE, CU_TENSOR_MAP_SWIZZLE_128B,
            CU_TENSOR_MAP_L2_PROMOTION_L2_128B, CU_TENSOR_MAP_FLOAT_OOB_FILL_NONE);
    }
    {
        cuuint64_t dims[2]    = {(cuuint64_t)K_DIM, (cuuint64_t)M_DIM};
        cuuint64_t strides[1] = {(cuuint64_t)K_DIM * sizeof(__half)};
        cuuint32_t box[2]     = {64u, (cuuint32_t)M_DIM};   // 128B x 256 rows
        cuuint32_t es[2]      = {1, 1};
        enc(&tmB, CU_TENSOR_MAP_DATA_TYPE_FLOAT16, 2, wh_ptr,
            dims, strides, box, es,
            CU_TENSOR_MAP_INTERLEAVE_NONE, CU_TENSOR_MAP_SWIZZLE_128B,
            CU_TENSOR_MAP_L2_PROMOTION_L2_128B, CU_TENSOR_MAP_FLOAT_OOB_FILL_NONE);
    }

    static bool attr_set = false;
    if (!attr_set) {
        cudaFuncSetAttribute(gat_kernel,
                             cudaFuncAttributeMaxDynamicSharedMemorySize,
                             SMEM_TOTAL);
        attr_set = true;
    }
    const int grid = N_ROWS / BM;   // 3125 (exact)
    gat_kernel<<<grid, THREADS, SMEM_TOTAL>>>(tmA, tmB, adj, out);
}

// round 9
// speedup vs baseline: 1.2093x; 1.2093x over previous
#include <cuda.h>
#include <cuda_runtime.h>
#include <cuda_fp16.h>
#include <cstdint>

// ============================================================================
// out = elu( (adj>0 ? (input@W)/cnt_row : 0) ), cnt_row = #(adj>0 in row);
// cnt==0 rows: softmax of all-(-9e15) is uniform 1/256.
// R9: R8 regressed (1-stage A32 + head-of-line convert => exposed TMA).
//     Back to R7 buffers (2-stage A32, 2-stage B, single A16, 108KB, 2 CTA/SM),
//     but: MMA(i) BEFORE convert(i+1) (TMA-A wait off critical path), and the
//     A16 write hazard handled by a 256-count mbarrier whose wait overlaps the
//     convert's LDS+cvt latency. One __syncthreads per iter.
// ============================================================================

#define N_ROWS 200000
#define K_DIM  512
#define M_DIM  256
#define BM     64
#define BK     64
#define NITER  (K_DIM / BK)     // 8
#define THREADS 256             // 8 warps: 2 (m) x 4 (n), warp tile 32x64

// --- shared memory layout (bytes) --------------------------------------------
#define MBAR_A(s)  ((s) * 8)            // 0, 8
#define MBAR_B(s)  (16 + (s) * 8)       // 16, 24
#define MBAR_FD    32                   // frag-done, count 256
#define MASK_OFF   128
#define CNT_OFF    (MASK_OFF + 64 * 8 * 4)      // 2176
#define A16_OFF    3584                 // 8KB single
#define A32_OFF(s) (12288 + (s) * 16384)
#define B_OFF(s)   (45056 + (s) * 32768)
#define SMEM_TOTAL 110592               // 108KB -> 2 CTAs/SM (proven in R7)
#define TXA        16384
#define TXB        32768

// --- device scratch: W transposed to [M][K], fp16 RN --------------------------
__device__ __half g_Wh[M_DIM * K_DIM];

// ============================================================================
// helpers (plain sm_90-level PTX; no 'a' features)
// ============================================================================
__device__ __forceinline__ uint32_t smem_u32(const void* p) {
    uint32_t a;
    asm("{ .reg .u64 t; cvta.to.shared.u64 t, %1; cvt.u32.u64 %0, t; }"
        : "=r"(a) : "l"(p));
    return a;
}
#define MBARRIER_INIT(mbar, count) \
    asm volatile("mbarrier.init.shared.b64 [%0], %1;" \
        :: "r"((uint32_t)(mbar)), "r"((uint32_t)(count)) : "memory")
#define MBARRIER_EXPECT_TX(mbar, bytes) \
    asm volatile("mbarrier.arrive.expect_tx.shared.b64 _, [%0], %1;" \
        :: "r"((uint32_t)(mbar)), "r"((uint32_t)(bytes)) : "memory")
#define MBARRIER_ARRIVE(mbar) \
    asm volatile("mbarrier.arrive.release.cta.shared.b64 _, [%0];" \
        :: "r"((uint32_t)(mbar)) : "memory")
#define MBARRIER_WAIT_PARITY(mbar, parity) do { \
    uint32_t _mbar = (uint32_t)(mbar); \
    uint32_t _par = (uint32_t)(parity); \
    uint32_t _done; \
    asm volatile( \
        "{\n\t.reg .pred p;\n\t" \
        "mbarrier.try_wait.parity.acquire.cta.shared::cta.b64 p, [%1], %2;\n\t" \
        "selp.b32 %0, 1, 0, p;\n\t}" \
        : "=r"(_done) : "r"(_mbar), "r"(_par) : "memory"); \
    if (!_done) { \
        asm volatile( \
            "{\n\t.reg .pred P1;\n\t" \
            "WAIT_LOOP_%=:\n\t" \
            "mbarrier.try_wait.parity.acquire.cta.shared::cta.b64 P1, [%0], %1, 0x989680;\n\t" \
            "@P1 bra.uni WAIT_DONE_%=;\n\t" \
            "bra.uni WAIT_LOOP_%=;\n\t" \
            "WAIT_DONE_%=:\n\t}" \
            :: "r"(_mbar), "r"(_par) : "memory"); \
    } \
} while (0)
#define TMA_LOAD_2D(smem_addr, map_ptr, cx, cy, mbar) \
    asm volatile( \
        "cp.async.bulk.tensor.2d.shared::cta.global.tile.mbarrier::complete_tx::bytes " \
        "[%0], [%1, {%2, %3}], [%4];" \
        :: "r"((uint32_t)(smem_addr)), "l"(map_ptr), \
           "r"((int32_t)(cx)), "r"((int32_t)(cy)), "r"((uint32_t)(mbar)) \
        : "memory")

__device__ __forceinline__ float4 lds128f(uint32_t a) {
    float4 v;
    asm volatile("ld.shared.v4.f32 {%0,%1,%2,%3}, [%4];"
                 : "=f"(v.x), "=f"(v.y), "=f"(v.z), "=f"(v.w) : "r"(a));
    return v;
}
__device__ __forceinline__ void sts128(uint32_t a, uint32_t r0, uint32_t r1,
                                       uint32_t r2, uint32_t r3) {
    asm volatile("st.shared.v4.b32 [%0], {%1,%2,%3,%4};"
                 :: "r"(a), "r"(r0), "r"(r1), "r"(r2), "r"(r3) : "memory");
}
__device__ __forceinline__ void ldsm_x4(uint32_t* r, uint32_t addr) {
    asm volatile("ldmatrix.sync.aligned.m8n8.x4.shared.b16 {%0,%1,%2,%3}, [%4];"
                 : "=r"(r[0]), "=r"(r[1]), "=r"(r[2]), "=r"(r[3]) : "r"(addr));
}
__device__ __forceinline__ uint32_t packh2(float lo, float hi) {
    uint32_t d;
    asm("cvt.rn.f16x2.f32 %0, %1, %2;" : "=r"(d) : "f"(hi), "f"(lo));
    return d;
}
__device__ __forceinline__ void mma16816(float* c, const uint32_t* a,
                                         const uint32_t* b) {
    asm volatile(
        "mma.sync.aligned.m16n8k16.row.col.f32.f16.f16.f32 "
        "{%0,%1,%2,%3}, {%4,%5,%6,%7}, {%8,%9}, {%0,%1,%2,%3};"
        : "+f"(c[0]), "+f"(c[1]), "+f"(c[2]), "+f"(c[3])
        : "r"(a[0]), "r"(a[1]), "r"(a[2]), "r"(a[3]), "r"(b[0]), "r"(b[1]));
}

// ============================================================================
// prep: W [K=512, M=256] row-major fp32 -> g_Wh [M][K] fp16 (RN)
// ============================================================================
__global__ void prep_wh_kernel(const float* __restrict__ W) {
    int idx = blockIdx.x * blockDim.x + threadIdx.x;
    int k = idx >> 8;
    int m = idx & 255;
    g_Wh[m * K_DIM + k] = __float2half_rn(W[idx]);
}

// ============================================================================
// fused GEMM (TMA + split-phase convert + ldmatrix + mma.sync) + attention
// ============================================================================
__global__ void __launch_bounds__(THREADS, 2) gat_kernel(
    const __grid_constant__ CUtensorMap tmap_a,
    const __grid_constant__ CUtensorMap tmap_b,
    const int* __restrict__ adj,
    float* __restrict__ out)
{
    extern __shared__ char smem[];
    const uint32_t sb = smem_u32(smem);
    uint32_t* smask = (uint32_t*)(smem + MASK_OFF);   // [64][8]
    int* scnt = (int*)(smem + CNT_OFF);               // [64][4]

    const int tid  = threadIdx.x;
    const int lane = tid & 31;
    const int wid  = tid >> 5;
    const int wm   = wid >> 2;   // 0..1 : 32-row band
    const int wn   = wid & 3;    // 0..3 : 64-col band
    const int tile = blockIdx.x * BM;

    // ---- mbarrier init + TMA prologue -----------------------------------------
    if (tid == 0) {
        MBARRIER_INIT(sb + MBAR_A(0), 1);
        MBARRIER_INIT(sb + MBAR_A(1), 1);
        MBARRIER_INIT(sb + MBAR_B(0), 1);
        MBARRIER_INIT(sb + MBAR_B(1), 1);
        MBARRIER_INIT(sb + MBAR_FD, THREADS);
    }
    __syncthreads();
    if (tid == 0) {
        #pragma unroll
        for (int j = 0; j < 2; j++) {
            MBARRIER_EXPECT_TX(sb + MBAR_A(j), TXA);
            TMA_LOAD_2D(sb + A32_OFF(j),        &tmap_a, j * BK,      tile, sb + MBAR_A(j));
            TMA_LOAD_2D(sb + A32_OFF(j) + 8192, &tmap_a, j * BK + 32, tile, sb + MBAR_A(j));
            MBARRIER_EXPECT_TX(sb + MBAR_B(j), TXB);
            TMA_LOAD_2D(sb + B_OFF(j), &tmap_b, j * BK, 0, sb + MBAR_B(j));
        }
    }

    // ---- adj mask + count (overlaps TMA flight; 64 | N_ROWS, no clamps) --------
    {
        int r = tid >> 2;
        int q = tid & 3;
        const int4* ap = (const int4*)(adj + (size_t)(tile + r) * M_DIM + q * 64);
        int cnt = 0;
        #pragma unroll
        for (int g = 0; g < 2; g++) {
            uint32_t m = 0;
            #pragma unroll
            for (int w = 0; w < 8; w++) {
                int4 v = __ldg(ap + g * 8 + w);
                m |= (v.x > 0 ? 1u : 0u) << (w * 4 + 0);
                m |= (v.y > 0 ? 1u : 0u) << (w * 4 + 1);
                m |= (v.z > 0 ? 1u : 0u) << (w * 4 + 2);
                m |= (v.w > 0 ? 1u : 0u) << (w * 4 + 3);
            }
            smask[r * 8 + q * 2 + g] = m;
            cnt += __popc(m);
        }
        scnt[r * 4 + q] = cnt;
    }

    // ---- per-thread constants ----------------------------------------------------
    const int arow = lane >> 2;                 // 0..7

    // convert mapping: row cr = tid>>2, k-quarter cq = tid&3
    const int cr = tid >> 2;
    const int cq = tid & 3;
    const uint32_t crx = (uint32_t)(cr & 7) << 4;
    const uint32_t csrc_off = (uint32_t)(cq >> 1) * 8192 + (uint32_t)cr * 128;
    const uint32_t cu0 = (uint32_t)(cq & 1) * 4;
    const uint32_t cdst = sb + A16_OFF + (uint32_t)cr * 128;

    // ldmatrix lane addressing (SW128 XOR on 128B rows)
    const uint32_t l7 = lane & 7;
    const uint32_t lxor = l7 << 4;
    const uint32_t a_row = (uint32_t)(wm * 32) + l7 + ((lane >> 3) & 1) * 8;
    const uint32_t a_kseg = ((lane >> 4) & 1) * 16;
    const uint32_t a_base = sb + A16_OFF + a_row * 128;
    const uint32_t b_row = (uint32_t)(wn * 64) + l7 + ((lane >> 4) & 1) * 8;
    const uint32_t b_kseg = ((lane >> 3) & 1) * 16;
    const uint32_t b_base_off = b_row * 128;

    float c[2][8][4];
    #pragma unroll
    for (int mf = 0; mf < 2; mf++)
        #pragma unroll
        for (int nf = 0; nf < 8; nf++)
            #pragma unroll
            for (int e = 0; e < 4; e++) c[mf][nf][e] = 0.0f;

    // ---- prologue convert: chunk 0 -> A16 ----------------------------------------
    MBARRIER_WAIT_PARITY(sb + MBAR_A(0), 0);
    {
        const uint32_t src = sb + A32_OFF(0) + csrc_off;
        float4 f0 = lds128f(src + (((cu0 + 0) << 4) ^ crx));
        float4 f1 = lds128f(src + (((cu0 + 1) << 4) ^ crx));
        float4 f2 = lds128f(src + (((cu0 + 2) << 4) ^ crx));
        float4 f3 = lds128f(src + (((cu0 + 3) << 4) ^ crx));
        sts128(cdst + (((uint32_t)(cq * 2 + 0) << 4) ^ crx),
               packh2(f0.x, f0.y), packh2(f0.z, f0.w),
               packh2(f1.x, f1.y), packh2(f1.z, f1.w));
        sts128(cdst + (((uint32_t)(cq * 2 + 1) << 4) ^ crx),
               packh2(f2.x, f2.y), packh2(f2.z, f2.w),
               packh2(f3.x, f3.y), packh2(f3.z, f3.w));
    }
    __syncthreads();   // A16(chunk0) visible; A32 slot0 free

    // ---- mainloop: 8 x BK=64 --------------------------------------------------------
    #pragma unroll 1
    for (int i = 0; i < NITER; i++) {
        const int s = i & 1;
        const uint32_t ph = (uint32_t)((i >> 1) & 1);

        // phase 1: MMAs on chunk i (A16 ready from prev iter / prologue)
        MBARRIER_WAIT_PARITY(sb + MBAR_B(s), ph);
        {
            const uint32_t bB = sb + B_OFF(s) + b_base_off;
            #pragma unroll
            for (int ks = 0; ks < 4; ks++) {
                const uint32_t ak = ((uint32_t)ks * 32 + a_kseg) ^ lxor;
                const uint32_t bk = ((uint32_t)ks * 32 + b_kseg) ^ lxor;
                uint32_t ra[2][4];
                ldsm_x4(ra[0], a_base + ak);
                ldsm_x4(ra[1], a_base + 2048 + ak);
                #pragma unroll
                for (int np = 0; np < 4; np++) {
                    uint32_t rb[4];
                    ldsm_x4(rb, bB + (uint32_t)np * 2048 + bk);
                    mma16816(c[0][np * 2 + 0], ra[0], rb);
                    mma16816(c[0][np * 2 + 1], ra[0], rb + 2);
                    mma16816(c[1][np * 2 + 0], ra[1], rb);
                    mma16816(c[1][np * 2 + 1], ra[1], rb + 2);
                }
            }
        }
        MBARRIER_ARRIVE(sb + MBAR_FD);   // my A16 + B[s] reads complete

        // phase 2: convert chunk i+1 (LDS+cvt BEFORE the FD wait -> overlap)
        if (i + 1 < NITER) {
            MBARRIER_WAIT_PARITY(sb + MBAR_A(1 - s), (uint32_t)(((i + 1) >> 1) & 1));
            const uint32_t src = sb + A32_OFF(1 - s) + csrc_off;
            float4 f0 = lds128f(src + (((cu0 + 0) << 4) ^ crx));
            float4 f1 = lds128f(src + (((cu0 + 1) << 4) ^ crx));
            float4 f2 = lds128f(src + (((cu0 + 2) << 4) ^ crx));
            float4 f3 = lds128f(src + (((cu0 + 3) << 4) ^ crx));
            uint32_t h0 = packh2(f0.x, f0.y), h1 = packh2(f0.z, f0.w);
            uint32_t h2 = packh2(f1.x, f1.y), h3 = packh2(f1.z, f1.w);
            uint32_t h4 = packh2(f2.x, f2.y), h5 = packh2(f2.z, f2.w);
            uint32_t h6 = packh2(f3.x, f3.y), h7 = packh2(f3.z, f3.w);
            // wait all CTA threads finished reading A16(chunk i)
            MBARRIER_WAIT_PARITY(sb + MBAR_FD, (uint32_t)(i & 1));
            sts128(cdst + (((uint32_t)(cq * 2 + 0) << 4) ^ crx), h0, h1, h2, h3);
            sts128(cdst + (((uint32_t)(cq * 2 + 1) << 4) ^ crx), h4, h5, h6, h7);
        }
        __syncthreads();   // A16(chunk i+1) visible; A32[1-s] + B[s] free

        // refill chunk i+2 into slot s (A32[s] freed at iter i-1's phase2)
        if (tid == 0 && i + 2 < NITER) {
            const int j = i + 2;
            MBARRIER_EXPECT_TX(sb + MBAR_A(s), TXA);
            TMA_LOAD_2D(sb + A32_OFF(s),        &tmap_a, j * BK,      tile, sb + MBAR_A(s));
            TMA_LOAD_2D(sb + A32_OFF(s) + 8192, &tmap_a, j * BK + 32, tile, sb + MBAR_A(s));
            MBARRIER_EXPECT_TX(sb + MBAR_B(s), TXB);
            TMA_LOAD_2D(sb + B_OFF(s), &tmap_b, j * BK, 0, sb + MBAR_B(s));
        }
    }

    // ---- epilogue: scale by 1/cnt on mask, elu, store -------------------------------
    #pragma unroll
    for (int mf = 0; mf < 2; mf++) {
        const int r0 = wm * 32 + mf * 16 + arow;
        #pragma unroll
        for (int half = 0; half < 2; half++) {
            const int rr = r0 + half * 8;
            const int grow = tile + rr;
            const int cnt = scnt[rr * 4] + scnt[rr * 4 + 1] +
                            scnt[rr * 4 + 2] + scnt[rr * 4 + 3];
            const bool all_on = (cnt == 0);
            const float scale = all_on ? (1.0f / 256.0f) : (1.0f / (float)cnt);
            #pragma unroll
            for (int nf = 0; nf < 8; nf++) {
                const int col = wn * 64 + nf * 8 + (int)(lane & 3) * 2;
                const uint32_t mw = smask[rr * 8 + (col >> 5)];
                float2 o;
                #pragma unroll
                for (int e = 0; e < 2; e++) {
                    float h = c[mf][nf][half * 2 + e];
                    bool on = all_on | (((mw >> ((col + e) & 31)) & 1u) != 0u);
                    float v = on ? h * scale : 0.0f;
                    float res = (v > 0.0f) ? v : (__expf(v) - 1.0f);
                    ((float*)&o)[e] = res;
                }
                *(float2*)(out + (size_t)grow * M_DIM + col) = o;
            }
        }
    }
}

// ============================================================================
// host launch
// ============================================================================
typedef CUresult (*EncodeTiledFn)(
    CUtensorMap*, CUtensorMapDataType, cuuint32_t, void*,
    const cuuint64_t*, const cuuint64_t*, const cuuint32_t*, const cuuint32_t*,
    CUtensorMapInterleave, CUtensorMapSwizzle, CUtensorMapL2promotion,
    CUtensorMapFloatOOBfill);

extern "C" void kernel_launch(void* const* d_in, const int* in_sizes, int n_in,
                              void* d_out, int out_size) {
    const float* inp = (const float*)d_in[0];
    const int*   adj = (const int*)d_in[1];
    const float* W   = (const float*)d_in[2];
    // d_in[3] ('a') provably cancels in the softmax; unused.
    float* out = (float*)d_out;

    prep_wh_kernel<<<(K_DIM * M_DIM) / 256, 256>>>(W);

    void* wh_ptr = nullptr;
    cudaGetSymbolAddress(&wh_ptr, g_Wh);

    void* fp = nullptr;
    cudaDriverEntryPointQueryResult qres;
    cudaGetDriverEntryPointByVersion("cuTensorMapEncodeTiled", &fp, 12000,
                                     cudaEnableDefault, &qres);
    EncodeTiledFn enc = (EncodeTiledFn)fp;

    alignas(64) CUtensorMap tmA;
    alignas(64) CUtensorMap tmB;
    {
        cuuint64_t dims[2]    = {(cuuint64_t)K_DIM, (cuuint64_t)N_ROWS};
        cuuint64_t strides[1] = {(cuuint64_t)K_DIM * sizeof(float)};
        cuuint32_t box[2]     = {32u, (cuuint32_t)BM};      // 128B x 64 rows
        cuuint32_t es[2]      = {1, 1};
        enc(&tmA, CU_TENSOR_MAP_DATA_TYPE_FLOAT32, 2, (void*)inp,
            dims, strides, box, es,
            CU_TENSOR_MAP_INTERLEAVE_NONE, CU_TENSOR_MAP_SWIZZLE_128B,
            CU_TENSOR_MAP_L2_PROMOTION_L2_128B, CU_TENSOR_MAP_FLOAT_OOB_FILL_NONE);
    }
    {
        cuuint64_t dims[2]    = {(cuuint64_t)K_DIM, (cuuint64_t)M_DIM};
        cuuint64_t strides[1] = {(cuuint64_t)K_DIM * sizeof(__half)};
        cuuint32_t box[2]     = {64u, (cuuint32_t)M_DIM};   // 128B x 256 rows
        cuuint32_t es[2]      = {1, 1};
        enc(&tmB, CU_TENSOR_MAP_DATA_TYPE_FLOAT16, 2, wh_ptr,
            dims, strides, box, es,
            CU_TENSOR_MAP_INTERLEAVE_NONE, CU_TENSOR_MAP_SWIZZLE_128B,
            CU_TENSOR_MAP_L2_PROMOTION_L2_128B, CU_TENSOR_MAP_FLOAT_OOB_FILL_NONE);
    }

    static bool attr_set = false;
    if (!attr_set) {
        cudaFuncSetAttribute(gat_kernel,
                             cudaFuncAttributeMaxDynamicSharedMemorySize,
                             SMEM_TOTAL);
        attr_set = true;
    }
    const int grid = N_ROWS / BM;   // 3125 (exact)
    gat_kernel<<<grid, THREADS, SMEM_TOTAL>>>(tmA, tmB, adj, out);
}

// round 10
// speedup vs baseline: 1.3182x; 1.0901x over previous
#include <cuda.h>
#include <cuda_runtime.h>
#include <cuda_fp16.h>
#include <cstdint>

// ============================================================================
// out = elu( (adj>0 ? (input@W)/cnt_row : 0) ), cnt_row = #(adj>0 in row);
// cnt==0 rows: softmax of all-(-9e15) is uniform 1/256.
// R10: R9 is L1-wavefront bound (frag re-reads). 4 warps @ 64x64 warp tiles
//      cut frag traffic 96KB->64KB/iter (B frags read exactly once). Same R9
//      pipeline (2-stage A32/B rings, MMA-first, FD split barrier), same smem
//      (108KB, 2 CTAs/SM); launch_bounds(128,2) -> 256-reg budget, no spills.
// ============================================================================

#define N_ROWS 200000
#define K_DIM  512
#define M_DIM  256
#define BM     64
#define BK     64
#define NITER  (K_DIM / BK)     // 8
#define THREADS 128             // 4 warps: 1 (m) x 4 (n), warp tile 64x64

// --- shared memory layout (bytes) --------------------------------------------
#define MBAR_A(s)  ((s) * 8)            // 0, 8
#define MBAR_B(s)  (16 + (s) * 8)       // 16, 24
#define MBAR_FD    32                   // frag-done, count 128
#define MASK_OFF   128                  // u32[64][8] -> 2176
#define CNT_OFF    (MASK_OFF + 64 * 8 * 4)      // int[64][2] -> 2688
#define A16_OFF    3584                 // 8KB single
#define A32_OFF(s) (12288 + (s) * 16384)
#define B_OFF(s)   (45056 + (s) * 32768)
#define SMEM_TOTAL 110592               // 108KB -> 2 CTAs/SM
#define TXA        16384
#define TXB        32768

// --- device scratch: W transposed to [M][K], fp16 RN --------------------------
__device__ __half g_Wh[M_DIM * K_DIM];

// ============================================================================
// helpers (plain sm_90-level PTX; no 'a' features)
// ============================================================================
__device__ __forceinline__ uint32_t smem_u32(const void* p) {
    uint32_t a;
    asm("{ .reg .u64 t; cvta.to.shared.u64 t, %1; cvt.u32.u64 %0, t; }"
        : "=r"(a) : "l"(p));
    return a;
}
#define MBARRIER_INIT(mbar, count) \
    asm volatile("mbarrier.init.shared.b64 [%0], %1;" \
        :: "r"((uint32_t)(mbar)), "r"((uint32_t)(count)) : "memory")
#define MBARRIER_EXPECT_TX(mbar, bytes) \
    asm volatile("mbarrier.arrive.expect_tx.shared.b64 _, [%0], %1;" \
        :: "r"((uint32_t)(mbar)), "r"((uint32_t)(bytes)) : "memory")
#define MBARRIER_ARRIVE(mbar) \
    asm volatile("mbarrier.arrive.release.cta.shared.b64 _, [%0];" \
        :: "r"((uint32_t)(mbar)) : "memory")
#define MBARRIER_WAIT_PARITY(mbar, parity) do { \
    uint32_t _mbar = (uint32_t)(mbar); \
    uint32_t _par = (uint32_t)(parity); \
    uint32_t _done; \
    asm volatile( \
        "{\n\t.reg .pred p;\n\t" \
        "mbarrier.try_wait.parity.acquire.cta.shared::cta.b64 p, [%1], %2;\n\t" \
        "selp.b32 %0, 1, 0, p;\n\t}" \
        : "=r"(_done) : "r"(_mbar), "r"(_par) : "memory"); \
    if (!_done) { \
        asm volatile( \
            "{\n\t.reg .pred P1;\n\t" \
            "WAIT_LOOP_%=:\n\t" \
            "mbarrier.try_wait.parity.acquire.cta.shared::cta.b64 P1, [%0], %1, 0x989680;\n\t" \
            "@P1 bra.uni WAIT_DONE_%=;\n\t" \
            "bra.uni WAIT_LOOP_%=;\n\t" \
            "WAIT_DONE_%=:\n\t}" \
            :: "r"(_mbar), "r"(_par) : "memory"); \
    } \
} while (0)
#define TMA_LOAD_2D(smem_addr, map_ptr, cx, cy, mbar) \
    asm volatile( \
        "cp.async.bulk.tensor.2d.shared::cta.global.tile.mbarrier::complete_tx::bytes " \
        "[%0], [%1, {%2, %3}], [%4];" \
        :: "r"((uint32_t)(smem_addr)), "l"(map_ptr), \
           "r"((int32_t)(cx)), "r"((int32_t)(cy)), "r"((uint32_t)(mbar)) \
        : "memory")

__device__ __forceinline__ float4 lds128f(uint32_t a) {
    float4 v;
    asm volatile("ld.shared.v4.f32 {%0,%1,%2,%3}, [%4];"
                 : "=f"(v.x), "=f"(v.y), "=f"(v.z), "=f"(v.w) : "r"(a));
    return v;
}
__device__ __forceinline__ void sts128(uint32_t a, uint32_t r0, uint32_t r1,
                                       uint32_t r2, uint32_t r3) {
    asm volatile("st.shared.v4.b32 [%0], {%1,%2,%3,%4};"
                 :: "r"(a), "r"(r0), "r"(r1), "r"(r2), "r"(r3) : "memory");
}
__device__ __forceinline__ void ldsm_x4(uint32_t* r, uint32_t addr) {
    asm volatile("ldmatrix.sync.aligned.m8n8.x4.shared.b16 {%0,%1,%2,%3}, [%4];"
                 : "=r"(r[0]), "=r"(r[1]), "=r"(r[2]), "=r"(r[3]) : "r"(addr));
}
__device__ __forceinline__ uint32_t packh2(float lo, float hi) {
    uint32_t d;
    asm("cvt.rn.f16x2.f32 %0, %1, %2;" : "=r"(d) : "f"(hi), "f"(lo));
    return d;
}
__device__ __forceinline__ void mma16816(float* c, const uint32_t* a,
                                         const uint32_t* b) {
    asm volatile(
        "mma.sync.aligned.m16n8k16.row.col.f32.f16.f16.f32 "
        "{%0,%1,%2,%3}, {%4,%5,%6,%7}, {%8,%9}, {%0,%1,%2,%3};"
        : "+f"(c[0]), "+f"(c[1]), "+f"(c[2]), "+f"(c[3])
        : "r"(a[0]), "r"(a[1]), "r"(a[2]), "r"(a[3]), "r"(b[0]), "r"(b[1]));
}

// ============================================================================
// prep: W [K=512, M=256] row-major fp32 -> g_Wh [M][K] fp16 (RN)
// ============================================================================
__global__ void prep_wh_kernel(const float* __restrict__ W) {
    int idx = blockIdx.x * blockDim.x + threadIdx.x;
    int k = idx >> 8;
    int m = idx & 255;
    g_Wh[m * K_DIM + k] = __float2half_rn(W[idx]);
}

// ============================================================================
// fused GEMM (TMA + split-phase convert + ldmatrix + mma.sync) + attention
// ============================================================================
__global__ void __launch_bounds__(THREADS, 2) gat_kernel(
    const __grid_constant__ CUtensorMap tmap_a,
    const __grid_constant__ CUtensorMap tmap_b,
    const int* __restrict__ adj,
    float* __restrict__ out)
{
    extern __shared__ char smem[];
    const uint32_t sb = smem_u32(smem);
    uint32_t* smask = (uint32_t*)(smem + MASK_OFF);   // [64][8]
    int* scnt = (int*)(smem + CNT_OFF);               // [64][2]

    const int tid  = threadIdx.x;
    const int lane = tid & 31;
    const int wn   = tid >> 5;   // 0..3 : 64-col band (single m-band)
    const int tile = blockIdx.x * BM;

    // ---- mbarrier init + TMA prologue -----------------------------------------
    if (tid == 0) {
        MBARRIER_INIT(sb + MBAR_A(0), 1);
        MBARRIER_INIT(sb + MBAR_A(1), 1);
        MBARRIER_INIT(sb + MBAR_B(0), 1);
        MBARRIER_INIT(sb + MBAR_B(1), 1);
        MBARRIER_INIT(sb + MBAR_FD, THREADS);
    }
    __syncthreads();
    if (tid == 0) {
        #pragma unroll
        for (int j = 0; j < 2; j++) {
            MBARRIER_EXPECT_TX(sb + MBAR_A(j), TXA);
            TMA_LOAD_2D(sb + A32_OFF(j),        &tmap_a, j * BK,      tile, sb + MBAR_A(j));
            TMA_LOAD_2D(sb + A32_OFF(j) + 8192, &tmap_a, j * BK + 32, tile, sb + MBAR_A(j));
            MBARRIER_EXPECT_TX(sb + MBAR_B(j), TXB);
            TMA_LOAD_2D(sb + B_OFF(j), &tmap_b, j * BK, 0, sb + MBAR_B(j));
        }
    }

    // ---- adj mask + count (overlaps TMA flight; 64 | N_ROWS) -------------------
    {
        int r = tid >> 1;            // 0..63
        int h = tid & 1;             // 128-col half
        const int4* ap = (const int4*)(adj + (size_t)(tile + r) * M_DIM + h * 128);
        int cnt = 0;
        #pragma unroll
        for (int g = 0; g < 4; g++) {
            uint32_t m = 0;
            #pragma unroll
            for (int w = 0; w < 8; w++) {
                int4 v = __ldg(ap + g * 8 + w);
                m |= (v.x > 0 ? 1u : 0u) << (w * 4 + 0);
                m |= (v.y > 0 ? 1u : 0u) << (w * 4 + 1);
                m |= (v.z > 0 ? 1u : 0u) << (w * 4 + 2);
                m |= (v.w > 0 ? 1u : 0u) << (w * 4 + 3);
            }
            smask[r * 8 + h * 4 + g] = m;
            cnt += __popc(m);
        }
        scnt[r * 2 + h] = cnt;
    }

    // ---- per-thread constants ----------------------------------------------------
    const int arow = lane >> 2;                 // 0..7

    // convert mapping: row cr = tid&63, subtile sub = tid>>6 (k-half of BK=64)
    const int cr  = tid & 63;
    const int sub = tid >> 6;                   // 0..1
    const uint32_t crx = (uint32_t)(cr & 7) << 4;
    const uint32_t csrc_off = (uint32_t)sub * 8192 + (uint32_t)cr * 128;
    const uint32_t cdst = sb + A16_OFF + (uint32_t)cr * 128;
    const uint32_t cdu0 = (uint32_t)sub * 4;    // dest 16B-unit base

    // ldmatrix lane addressing (SW128 XOR on 128B rows)
    const uint32_t l7 = lane & 7;
    const uint32_t lxor = l7 << 4;
    const uint32_t a_row = l7 + ((lane >> 3) & 1) * 8;       // within 16-row frag
    const uint32_t a_kseg = ((lane >> 4) & 1) * 16;
    const uint32_t a_base = sb + A16_OFF + a_row * 128;      // + mf*2048
    const uint32_t b_row = (uint32_t)(wn * 64) + l7 + ((lane >> 4) & 1) * 8;
    const uint32_t b_kseg = ((lane >> 3) & 1) * 16;
    const uint32_t b_base_off = b_row * 128;

    float c[4][8][4];
    #pragma unroll
    for (int mf = 0; mf < 4; mf++)
        #pragma unroll
        for (int nf = 0; nf < 8; nf++)
            #pragma unroll
            for (int e = 0; e < 4; e++) c[mf][nf][e] = 0.0f;

    // ---- prologue convert: chunk 0 -> A16 ----------------------------------------
    MBARRIER_WAIT_PARITY(sb + MBAR_A(0), 0);
    {
        const uint32_t src = sb + A32_OFF(0) + csrc_off;
        #pragma unroll
        for (int j = 0; j < 2; j++) {
            float4 f0 = lds128f(src + (((uint32_t)(j * 4 + 0) << 4) ^ crx));
            float4 f1 = lds128f(src + (((uint32_t)(j * 4 + 1) << 4) ^ crx));
            float4 f2 = lds128f(src + (((uint32_t)(j * 4 + 2) << 4) ^ crx));
            float4 f3 = lds128f(src + (((uint32_t)(j * 4 + 3) << 4) ^ crx));
            sts128(cdst + (((cdu0 + j * 2 + 0) << 4) ^ crx),
                   packh2(f0.x, f0.y), packh2(f0.z, f0.w),
                   packh2(f1.x, f1.y), packh2(f1.z, f1.w));
            sts128(cdst + (((cdu0 + j * 2 + 1) << 4) ^ crx),
                   packh2(f2.x, f2.y), packh2(f2.z, f2.w),
                   packh2(f3.x, f3.y), packh2(f3.z, f3.w));
        }
    }
    __syncthreads();   // A16(chunk0) visible; A32 slot0 free

    // ---- mainloop: 8 x BK=64 --------------------------------------------------------
    #pragma unroll 1
    for (int i = 0; i < NITER; i++) {
        const int s = i & 1;
        const uint32_t ph = (uint32_t)((i >> 1) & 1);

        // phase 1: MMAs on chunk i
        MBARRIER_WAIT_PARITY(sb + MBAR_B(s), ph);
        {
            const uint32_t bB = sb + B_OFF(s) + b_base_off;
            #pragma unroll
            for (int ks = 0; ks < 4; ks++) {
                const uint32_t ak = ((uint32_t)ks * 32 + a_kseg) ^ lxor;
                const uint32_t bk = ((uint32_t)ks * 32 + b_kseg) ^ lxor;
                uint32_t ra[4][4];
                #pragma unroll
                for (int mf = 0; mf < 4; mf++)
                    ldsm_x4(ra[mf], a_base + (uint32_t)mf * 2048 + ak);
                #pragma unroll
                for (int np = 0; np < 4; np++) {
                    uint32_t rb[4];
                    ldsm_x4(rb, bB + (uint32_t)np * 2048 + bk);
                    #pragma unroll
                    for (int mf = 0; mf < 4; mf++) {
                        mma16816(c[mf][np * 2 + 0], ra[mf], rb);
                        mma16816(c[mf][np * 2 + 1], ra[mf], rb + 2);
                    }
                }
            }
        }
        MBARRIER_ARRIVE(sb + MBAR_FD);   // my A16 + B[s] reads complete

        // phase 2: convert chunk i+1 (LDS+cvt BEFORE the FD wait -> overlap)
        if (i + 1 < NITER) {
            MBARRIER_WAIT_PARITY(sb + MBAR_A(1 - s), (uint32_t)(((i + 1) >> 1) & 1));
            const uint32_t src = sb + A32_OFF(1 - s) + csrc_off;
            float4 f[8];
            #pragma unroll
            for (int u = 0; u < 8; u++)
                f[u] = lds128f(src + (((uint32_t)u << 4) ^ crx));
            uint32_t h[16];
            #pragma unroll
            for (int u = 0; u < 8; u++) {
                h[u * 2 + 0] = packh2(f[u].x, f[u].y);
                h[u * 2 + 1] = packh2(f[u].z, f[u].w);
            }
            // wait all CTA threads finished reading A16(chunk i)
            MBARRIER_WAIT_PARITY(sb + MBAR_FD, (uint32_t)(i & 1));
            #pragma unroll
            for (int j = 0; j < 4; j++)
                sts128(cdst + (((cdu0 + j) << 4) ^ crx),
                       h[j * 4 + 0], h[j * 4 + 1], h[j * 4 + 2], h[j * 4 + 3]);
        }
        __syncthreads();   // A16(chunk i+1) visible; A32[1-s] + B[s] free

        // refill chunk i+2 into slot s
        if (tid == 0 && i + 2 < NITER) {
            const int j = i + 2;
            MBARRIER_EXPECT_TX(sb + MBAR_A(s), TXA);
            TMA_LOAD_2D(sb + A32_OFF(s),        &tmap_a, j * BK,      tile, sb + MBAR_A(s));
            TMA_LOAD_2D(sb + A32_OFF(s) + 8192, &tmap_a, j * BK + 32, tile, sb + MBAR_A(s));
            MBARRIER_EXPECT_TX(sb + MBAR_B(s), TXB);
            TMA_LOAD_2D(sb + B_OFF(s), &tmap_b, j * BK, 0, sb + MBAR_B(s));
        }
    }

    // ---- epilogue: scale by 1/cnt on mask, elu, store -------------------------------
    #pragma unroll
    for (int mf = 0; mf < 4; mf++) {
        const int r0 = mf * 16 + arow;
        #pragma unroll
        for (int half = 0; half < 2; half++) {
            const int rr = r0 + half * 8;
            const int grow = tile + rr;
            const int cnt = scnt[rr * 2] + scnt[rr * 2 + 1];
            const bool all_on = (cnt == 0);
            const float scale = all_on ? (1.0f / 256.0f) : (1.0f / (float)cnt);
            #pragma unroll
            for (int nf = 0; nf < 8; nf++) {
                const int col = wn * 64 + nf * 8 + (int)(lane & 3) * 2;
                const uint32_t mw = smask[rr * 8 + (col >> 5)];
                float2 o;
                #pragma unroll
                for (int e = 0; e < 2; e++) {
                    float h = c[mf][nf][half * 2 + e];
                    bool on = all_on | (((mw >> ((col + e) & 31)) & 1u) != 0u);
                    float v = on ? h * scale : 0.0f;
                    float res = (v > 0.0f) ? v : (__expf(v) - 1.0f);
                    ((float*)&o)[e] = res;
                }
                *(float2*)(out + (size_t)grow * M_DIM + col) = o;
            }
        }
    }
}

// ============================================================================
// host launch
// ============================================================================
typedef CUresult (*EncodeTiledFn)(
    CUtensorMap*, CUtensorMapDataType, cuuint32_t, void*,
    const cuuint64_t*, const cuuint64_t*, const cuuint32_t*, const cuuint32_t*,
    CUtensorMapInterleave, CUtensorMapSwizzle, CUtensorMapL2promotion,
    CUtensorMapFloatOOBfill);

extern "C" void kernel_launch(void* const* d_in, const int* in_sizes, int n_in,
                              void* d_out, int out_size) {
    const float* inp = (const float*)d_in[0];
    const int*   adj = (const int*)d_in[1];
    const float* W   = (const float*)d_in[2];
    // d_in[3] ('a') provably cancels in the softmax; unused.
    float* out = (float*)d_out;

    prep_wh_kernel<<<(K_DIM * M_DIM) / 256, 256>>>(W);

    void* wh_ptr = nullptr;
    cudaGetSymbolAddress(&wh_ptr, g_Wh);

    void* fp = nullptr;
    cudaDriverEntryPointQueryResult qres;
    cudaGetDriverEntryPointByVersion("cuTensorMapEncodeTiled", &fp, 12000,
                                     cudaEnableDefault, &qres);
    EncodeTiledFn enc = (EncodeTiledFn)fp;

    alignas(64) CUtensorMap tmA;
    alignas(64) CUtensorMap tmB;
    {
        cuuint64_t dims[2]    = {(cuuint64_t)K_DIM, (cuuint64_t)N_ROWS};
        cuuint64_t strides[1] = {(cuuint64_t)K_DIM * sizeof(float)};
        cuuint32_t box[2]     = {32u, (cuuint32_t)BM};      // 128B x 64 rows
        cuuint32_t es[2]      = {1, 1};
        enc(&tmA, CU_TENSOR_MAP_DATA_TYPE_FLOAT32, 2, (void*)inp,
            dims, strides, box, es,
            CU_TENSOR_MAP_INTERLEAVE_NONE, CU_TENSOR_MAP_SWIZZLE_128B,
            CU_TENSOR_MAP_L2_PROMOTION_L2_128B, CU_TENSOR_MAP_FLOAT_OOB_FILL_NONE);
    }
    {
        cuuint64_t dims[2]    = {(cuuint64_t)K_DIM, (cuuint64_t)M_DIM};
        cuuint64_t strides[1] = {(cuuint64_t)K_DIM * sizeof(__half)};
        cuuint32_t box[2]     = {64u, (cuuint32_t)M_DIM};   // 128B x 256 rows
        cuuint32_t es[2]      = {1, 1};
        enc(&tmB, CU_TENSOR_MAP_DATA_TYPE_FLOAT16, 2, wh_ptr,
            dims, strides, box, es,
            CU_TENSOR_MAP_INTERLEAVE_NONE, CU_TENSOR_MAP_SWIZZLE_128B,
            CU_TENSOR_MAP_L2_PROMOTION_L2_128B, CU_TENSOR_MAP_FLOAT_OOB_FILL_NONE);
    }

    static bool attr_set = false;
    if (!attr_set) {
        cudaFuncSetAttribute(gat_kernel,
                             cudaFuncAttributeMaxDynamicSharedMemorySize,
                             SMEM_TOTAL);
        attr_set = true;
    }
    const int grid = N_ROWS / BM;   // 3125 (exact)
    gat_kernel<<<grid, THREADS, SMEM_TOTAL>>>(tmA, tmB, adj, out);
}

// round 11
// speedup vs baseline: 1.5047x; 1.1415x over previous
#include <cuda.h>
#include <cuda_runtime.h>
#include <cuda_fp16.h>
#include <cstdint>

// ============================================================================
// out = elu( (adj>0 ? (input@W)/cnt_row : 0) ), cnt_row = #(adj>0 in row);
// cnt==0 rows: softmax of all-(-9e15) is uniform 1/256.
// R11: R10 exposure-bound at 8 warps/SM (occ 12.3%, nothing saturated).
//      BK=32 redesign -> 64KB smem -> 3 CTAs/SM (12 warps): A32 3x8KB SW128,
//      B 2x16KB SW64 (64B rows), A16 4KB SW64. Same MMA-first + FD-split
//      pipeline, NITER=16. launch_bounds(128,3).
// ============================================================================

#define N_ROWS 200000
#define K_DIM  512
#define M_DIM  256
#define BM     64
#define BK     32
#define NITER  (K_DIM / BK)     // 16
#define THREADS 128             // 4 warps: 1 (m) x 4 (n), warp tile 64x64

// --- shared memory layout (bytes) --------------------------------------------
#define MBAR_A(s)  ((s) * 8)            // 0, 8, 16
#define MBAR_B(s)  (24 + (s) * 8)       // 24, 32
#define MBAR_FD    40                   // frag-done, count 128
#define MASK_OFF   128                  // u32[64][8] -> 2176
#define CNT_OFF    (MASK_OFF + 64 * 8 * 4)      // int[64][2] -> 2688
#define A16_OFF    4096                 // 4KB (64 x 64B rows, SW64)
#define A32_OFF(s) (8192 + (s) * 8192)  // 3 x 8KB (64 x 128B rows, SW128)
#define B_OFF(s)   (32768 + (s) * 16384) // 2 x 16KB (256 x 64B rows, SW64)
#define SMEM_TOTAL 65536                // 64KB -> 3 CTAs/SM
#define TXA        8192
#define TXB        16384

// --- device scratch: W transposed to [M][K], fp16 RN --------------------------
__device__ __half g_Wh[M_DIM * K_DIM];

// ============================================================================
// helpers (plain sm_90-level PTX; no 'a' features)
// ============================================================================
__device__ __forceinline__ uint32_t smem_u32(const void* p) {
    uint32_t a;
    asm("{ .reg .u64 t; cvta.to.shared.u64 t, %1; cvt.u32.u64 %0, t; }"
        : "=r"(a) : "l"(p));
    return a;
}
#define MBARRIER_INIT(mbar, count) \
    asm volatile("mbarrier.init.shared.b64 [%0], %1;" \
        :: "r"((uint32_t)(mbar)), "r"((uint32_t)(count)) : "memory")
#define MBARRIER_EXPECT_TX(mbar, bytes) \
    asm volatile("mbarrier.arrive.expect_tx.shared.b64 _, [%0], %1;" \
        :: "r"((uint32_t)(mbar)), "r"((uint32_t)(bytes)) : "memory")
#define MBARRIER_ARRIVE(mbar) \
    asm volatile("mbarrier.arrive.release.cta.shared.b64 _, [%0];" \
        :: "r"((uint32_t)(mbar)) : "memory")
#define MBARRIER_WAIT_PARITY(mbar, parity) do { \
    uint32_t _mbar = (uint32_t)(mbar); \
    uint32_t _par = (uint32_t)(parity); \
    uint32_t _done; \
    asm volatile( \
        "{\n\t.reg .pred p;\n\t" \
        "mbarrier.try_wait.parity.acquire.cta.shared::cta.b64 p, [%1], %2;\n\t" \
        "selp.b32 %0, 1, 0, p;\n\t}" \
        : "=r"(_done) : "r"(_mbar), "r"(_par) : "memory"); \
    if (!_done) { \
        asm volatile( \
            "{\n\t.reg .pred P1;\n\t" \
            "WAIT_LOOP_%=:\n\t" \
            "mbarrier.try_wait.parity.acquire.cta.shared::cta.b64 P1, [%0], %1, 0x989680;\n\t" \
            "@P1 bra.uni WAIT_DONE_%=;\n\t" \
            "bra.uni WAIT_LOOP_%=;\n\t" \
            "WAIT_DONE_%=:\n\t}" \
            :: "r"(_mbar), "r"(_par) : "memory"); \
    } \
} while (0)
#define TMA_LOAD_2D(smem_addr, map_ptr, cx, cy, mbar) \
    asm volatile( \
        "cp.async.bulk.tensor.2d.shared::cta.global.tile.mbarrier::complete_tx::bytes " \
        "[%0], [%1, {%2, %3}], [%4];" \
        :: "r"((uint32_t)(smem_addr)), "l"(map_ptr), \
           "r"((int32_t)(cx)), "r"((int32_t)(cy)), "r"((uint32_t)(mbar)) \
        : "memory")

__device__ __forceinline__ float4 lds128f(uint32_t a) {
    float4 v;
    asm volatile("ld.shared.v4.f32 {%0,%1,%2,%3}, [%4];"
                 : "=f"(v.x), "=f"(v.y), "=f"(v.z), "=f"(v.w) : "r"(a));
    return v;
}
__device__ __forceinline__ void sts128(uint32_t a, uint32_t r0, uint32_t r1,
                                       uint32_t r2, uint32_t r3) {
    asm volatile("st.shared.v4.b32 [%0], {%1,%2,%3,%4};"
                 :: "r"(a), "r"(r0), "r"(r1), "r"(r2), "r"(r3) : "memory");
}
__device__ __forceinline__ void ldsm_x4(uint32_t* r, uint32_t addr) {
    asm volatile("ldmatrix.sync.aligned.m8n8.x4.shared.b16 {%0,%1,%2,%3}, [%4];"
                 : "=r"(r[0]), "=r"(r[1]), "=r"(r[2]), "=r"(r[3]) : "r"(addr));
}
__device__ __forceinline__ uint32_t packh2(float lo, float hi) {
    uint32_t d;
    asm("cvt.rn.f16x2.f32 %0, %1, %2;" : "=r"(d) : "f"(hi), "f"(lo));
    return d;
}
__device__ __forceinline__ void mma16816(float* c, const uint32_t* a,
                                         const uint32_t* b) {
    asm volatile(
        "mma.sync.aligned.m16n8k16.row.col.f32.f16.f16.f32 "
        "{%0,%1,%2,%3}, {%4,%5,%6,%7}, {%8,%9}, {%0,%1,%2,%3};"
        : "+f"(c[0]), "+f"(c[1]), "+f"(c[2]), "+f"(c[3])
        : "r"(a[0]), "r"(a[1]), "r"(a[2]), "r"(a[3]), "r"(b[0]), "r"(b[1]));
}

// ============================================================================
// prep: W [K=512, M=256] row-major fp32 -> g_Wh [M][K] fp16 (RN)
// ============================================================================
__global__ void prep_wh_kernel(const float* __restrict__ W) {
    int idx = blockIdx.x * blockDim.x + threadIdx.x;
    int k = idx >> 8;
    int m = idx & 255;
    g_Wh[m * K_DIM + k] = __float2half_rn(W[idx]);
}

// ============================================================================
// fused GEMM (TMA + split-phase convert + ldmatrix + mma.sync) + attention
// ============================================================================
__global__ void __launch_bounds__(THREADS, 3) gat_kernel(
    const __grid_constant__ CUtensorMap tmap_a,
    const __grid_constant__ CUtensorMap tmap_b,
    const int* __restrict__ adj,
    float* __restrict__ out)
{
    extern __shared__ char smem[];
    const uint32_t sb = smem_u32(smem);
    uint32_t* smask = (uint32_t*)(smem + MASK_OFF);   // [64][8]
    int* scnt = (int*)(smem + CNT_OFF);               // [64][2]

    const int tid  = threadIdx.x;
    const int lane = tid & 31;
    const int wn   = tid >> 5;   // 0..3 : 64-col band (single m-band)
    const int tile = blockIdx.x * BM;

    // ---- mbarrier init + TMA prologue -----------------------------------------
    if (tid == 0) {
        MBARRIER_INIT(sb + MBAR_A(0), 1);
        MBARRIER_INIT(sb + MBAR_A(1), 1);
        MBARRIER_INIT(sb + MBAR_A(2), 1);
        MBARRIER_INIT(sb + MBAR_B(0), 1);
        MBARRIER_INIT(sb + MBAR_B(1), 1);
        MBARRIER_INIT(sb + MBAR_FD, THREADS);
    }
    __syncthreads();
    if (tid == 0) {
        #pragma unroll
        for (int j = 0; j < 3; j++) {
            MBARRIER_EXPECT_TX(sb + MBAR_A(j), TXA);
            TMA_LOAD_2D(sb + A32_OFF(j), &tmap_a, j * BK, tile, sb + MBAR_A(j));
        }
        #pragma unroll
        for (int j = 0; j < 2; j++) {
            MBARRIER_EXPECT_TX(sb + MBAR_B(j), TXB);
            TMA_LOAD_2D(sb + B_OFF(j), &tmap_b, j * BK, 0, sb + MBAR_B(j));
        }
    }

    // ---- adj mask + count (overlaps TMA flight; 64 | N_ROWS) -------------------
    {
        int r = tid >> 1;            // 0..63
        int h = tid & 1;             // 128-col half
        const int4* ap = (const int4*)(adj + (size_t)(tile + r) * M_DIM + h * 128);
        int cnt = 0;
        #pragma unroll
        for (int g = 0; g < 4; g++) {
            uint32_t m = 0;
            #pragma unroll
            for (int w = 0; w < 8; w++) {
                int4 v = __ldg(ap + g * 8 + w);
                m |= (v.x > 0 ? 1u : 0u) << (w * 4 + 0);
                m |= (v.y > 0 ? 1u : 0u) << (w * 4 + 1);
                m |= (v.z > 0 ? 1u : 0u) << (w * 4 + 2);
                m |= (v.w > 0 ? 1u : 0u) << (w * 4 + 3);
            }
            smask[r * 8 + h * 4 + g] = m;
            cnt += __popc(m);
        }
        scnt[r * 2 + h] = cnt;
    }

    // ---- per-thread constants ----------------------------------------------------
    const int arow = lane >> 2;                 // 0..7 (epilogue)

    // convert mapping: row cr = tid>>1 (0..63), k-half sub = tid&1
    const int cr  = tid >> 1;
    const int sub = tid & 1;
    const uint32_t xr128 = (uint32_t)(cr & 7) << 4;        // src SW128 xor
    const uint32_t xr64  = (uint32_t)((cr >> 1) & 3) << 4; // dst SW64 xor
    const uint32_t csrc_row = (uint32_t)cr * 128;          // + A32_OFF(slot)
    const uint32_t csu = (uint32_t)sub * 4;                // src 16B-unit base
    const uint32_t cdst = sb + A16_OFF + (uint32_t)cr * 64;
    const uint32_t cdu = (uint32_t)sub * 2;                // dst 16B-unit base

    // ldmatrix lane addressing (SW64: unit ^= (row>>1)&3)
    const uint32_t l7 = lane & 7;
    const uint32_t sw64x = ((l7 >> 1) & 3) << 4;           // row-base mult of 8
    const uint32_t a_row = l7 + ((lane >> 3) & 1) * 8;
    const uint32_t a_kseg = (lane >> 4) & 1;
    const uint32_t a_base = sb + A16_OFF + a_row * 64;
    const uint32_t b_row = (uint32_t)(wn * 64) + l7 + ((lane >> 4) & 1) * 8;
    const uint32_t b_kseg = (lane >> 3) & 1;
    const uint32_t b_base_off = b_row * 64;

    float c[4][8][4];
    #pragma unroll
    for (int mf = 0; mf < 4; mf++)
        #pragma unroll
        for (int nf = 0; nf < 8; nf++)
            #pragma unroll
            for (int e = 0; e < 4; e++) c[mf][nf][e] = 0.0f;

    // ---- prologue convert: chunk 0 -> A16 ----------------------------------------
    MBARRIER_WAIT_PARITY(sb + MBAR_A(0), 0);
    {
        const uint32_t src = sb + A32_OFF(0) + csrc_row;
        float4 f0 = lds128f(src + (((csu + 0) << 4) ^ xr128));
        float4 f1 = lds128f(src + (((csu + 1) << 4) ^ xr128));
        float4 f2 = lds128f(src + (((csu + 2) << 4) ^ xr128));
        float4 f3 = lds128f(src + (((csu + 3) << 4) ^ xr128));
        sts128(cdst + (((cdu + 0) << 4) ^ xr64),
               packh2(f0.x, f0.y), packh2(f0.z, f0.w),
               packh2(f1.x, f1.y), packh2(f1.z, f1.w));
        sts128(cdst + (((cdu + 1) << 4) ^ xr64),
               packh2(f2.x, f2.y), packh2(f2.z, f2.w),
               packh2(f3.x, f3.y), packh2(f3.z, f3.w));
    }
    __syncthreads();   // A16(chunk0) visible

    // convert slot/phase counters (for chunk j = i+1, starting j=1)
    int ca_slot = 1, ca_ph = 0;
    // refill slot counter for chunk j = i+3 (starting j=3 -> slot 0)
    int rf_slot = 0;

    // ---- mainloop: 16 x BK=32 -------------------------------------------------------
    #pragma unroll 1
    for (int i = 0; i < NITER; i++) {
        // phase 1: MMAs on chunk i
        MBARRIER_WAIT_PARITY(sb + MBAR_B(i & 1), (uint32_t)((i >> 1) & 1));
        {
            const uint32_t bB = sb + B_OFF(i & 1) + b_base_off;
            #pragma unroll
            for (int ks = 0; ks < 2; ks++) {
                const uint32_t ak = (((uint32_t)ks * 2 + a_kseg) << 4) ^ sw64x;
                const uint32_t bk = (((uint32_t)ks * 2 + b_kseg) << 4) ^ sw64x;
                uint32_t ra[4][4];
                #pragma unroll
                for (int mf = 0; mf < 4; mf++)
                    ldsm_x4(ra[mf], a_base + (uint32_t)mf * 1024 + ak);
                #pragma unroll
                for (int np = 0; np < 4; np++) {
                    uint32_t rb[4];
                    ldsm_x4(rb, bB + (uint32_t)np * 1024 + bk);
                    #pragma unroll
                    for (int mf = 0; mf < 4; mf++) {
                        mma16816(c[mf][np * 2 + 0], ra[mf], rb);
                        mma16816(c[mf][np * 2 + 1], ra[mf], rb + 2);
                    }
                }
            }
        }
        MBARRIER_ARRIVE(sb + MBAR_FD);   // my A16 + B[i&1] reads complete

        // phase 2: convert chunk i+1 (LDS+cvt BEFORE the FD wait -> overlap)
        if (i + 1 < NITER) {
            MBARRIER_WAIT_PARITY(sb + MBAR_A(ca_slot), (uint32_t)ca_ph);
            const uint32_t src = sb + A32_OFF(ca_slot) + csrc_row;
            float4 f0 = lds128f(src + (((csu + 0) << 4) ^ xr128));
            float4 f1 = lds128f(src + (((csu + 1) << 4) ^ xr128));
            float4 f2 = lds128f(src + (((csu + 2) << 4) ^ xr128));
            float4 f3 = lds128f(src + (((csu + 3) << 4) ^ xr128));
            uint32_t h0 = packh2(f0.x, f0.y), h1 = packh2(f0.z, f0.w);
            uint32_t h2 = packh2(f1.x, f1.y), h3 = packh2(f1.z, f1.w);
            uint32_t h4 = packh2(f2.x, f2.y), h5 = packh2(f2.z, f2.w);
            uint32_t h6 = packh2(f3.x, f3.y), h7 = packh2(f3.z, f3.w);
            // wait all CTA threads finished reading A16(chunk i)
            MBARRIER_WAIT_PARITY(sb + MBAR_FD, (uint32_t)(i & 1));
            sts128(cdst + (((cdu + 0) << 4) ^ xr64), h0, h1, h2, h3);
            sts128(cdst + (((cdu + 1) << 4) ^ xr64), h4, h5, h6, h7);
            if (++ca_slot == 3) { ca_slot = 0; ca_ph ^= 1; }
        }
        __syncthreads();   // A16(chunk i+1) visible; A32[old] + B[i&1] free

        // refills: A chunk i+3 into slot rf_slot, B chunk i+2 into slot i&1
        if (tid == 0) {
            if (i + 3 < NITER) {
                MBARRIER_EXPECT_TX(sb + MBAR_A(rf_slot), TXA);
                TMA_LOAD_2D(sb + A32_OFF(rf_slot), &tmap_a, (i + 3) * BK, tile,
                            sb + MBAR_A(rf_slot));
            }
            if (i + 2 < NITER) {
                MBARRIER_EXPECT_TX(sb + MBAR_B(i & 1), TXB);
                TMA_LOAD_2D(sb + B_OFF(i & 1), &tmap_b, (i + 2) * BK, 0,
                            sb + MBAR_B(i & 1));
            }
        }
        if (++rf_slot == 3) rf_slot = 0;
    }

    // ---- epilogue: scale by 1/cnt on mask, elu, store -------------------------------
    #pragma unroll
    for (int mf = 0; mf < 4; mf++) {
        const int r0 = mf * 16 + arow;
        #pragma unroll
        for (int half = 0; half < 2; half++) {
            const int rr = r0 + half * 8;
            const int grow = tile + rr;
            const int cnt = scnt[rr * 2] + scnt[rr * 2 + 1];
            const bool all_on = (cnt == 0);
            const float scale = all_on ? (1.0f / 256.0f) : (1.0f / (float)cnt);
            #pragma unroll
            for (int nf = 0; nf < 8; nf++) {
                const int col = wn * 64 + nf * 8 + (int)(lane & 3) * 2;
                const uint32_t mw = smask[rr * 8 + (col >> 5)];
                float2 o;
                #pragma unroll
                for (int e = 0; e < 2; e++) {
                    float h = c[mf][nf][half * 2 + e];
                    bool on = all_on | (((mw >> ((col + e) & 31)) & 1u) != 0u);
                    float v = on ? h * scale : 0.0f;
                    float res = (v > 0.0f) ? v : (__expf(v) - 1.0f);
                    ((float*)&o)[e] = res;
                }
                *(float2*)(out + (size_t)grow * M_DIM + col) = o;
            }
        }
    }
}

// ============================================================================
// host launch
// ============================================================================
typedef CUresult (*EncodeTiledFn)(
    CUtensorMap*, CUtensorMapDataType, cuuint32_t, void*,
    const cuuint64_t*, const cuuint64_t*, const cuuint32_t*, const cuuint32_t*,
    CUtensorMapInterleave, CUtensorMapSwizzle, CUtensorMapL2promotion,
    CUtensorMapFloatOOBfill);

extern "C" void kernel_launch(void* const* d_in, const int* in_sizes, int n_in,
                              void* d_out, int out_size) {
    const float* inp = (const float*)d_in[0];
    const int*   adj = (const int*)d_in[1];
    const float* W   = (const float*)d_in[2];
    // d_in[3] ('a') provably cancels in the softmax; unused.
    float* out = (float*)d_out;

    prep_wh_kernel<<<(K_DIM * M_DIM) / 256, 256>>>(W);

    void* wh_ptr = nullptr;
    cudaGetSymbolAddress(&wh_ptr, g_Wh);

    void* fp = nullptr;
    cudaDriverEntryPointQueryResult qres;
    cudaGetDriverEntryPointByVersion("cuTensorMapEncodeTiled", &fp, 12000,
                                     cudaEnableDefault, &qres);
    EncodeTiledFn enc = (EncodeTiledFn)fp;

    alignas(64) CUtensorMap tmA;
    alignas(64) CUtensorMap tmB;
    {
        cuuint64_t dims[2]    = {(cuuint64_t)K_DIM, (cuuint64_t)N_ROWS};
        cuuint64_t strides[1] = {(cuuint64_t)K_DIM * sizeof(float)};
        cuuint32_t box[2]     = {32u, (cuuint32_t)BM};      // 128B x 64 rows
        cuuint32_t es[2]      = {1, 1};
        enc(&tmA, CU_TENSOR_MAP_DATA_TYPE_FLOAT32, 2, (void*)inp,
            dims, strides, box, es,
            CU_TENSOR_MAP_INTERLEAVE_NONE, CU_TENSOR_MAP_SWIZZLE_128B,
            CU_TENSOR_MAP_L2_PROMOTION_L2_128B, CU_TENSOR_MAP_FLOAT_OOB_FILL_NONE);
    }
    {
        cuuint64_t dims[2]    = {(cuuint64_t)K_DIM, (cuuint64_t)M_DIM};
        cuuint64_t strides[1] = {(cuuint64_t)K_DIM * sizeof(__half)};
        cuuint32_t box[2]     = {32u, (cuuint32_t)M_DIM};   // 64B x 256 rows
        cuuint32_t es[2]      = {1, 1};
        enc(&tmB, CU_TENSOR_MAP_DATA_TYPE_FLOAT16, 2, wh_ptr,
            dims, strides, box, es,
            CU_TENSOR_MAP_INTERLEAVE_NONE, CU_TENSOR_MAP_SWIZZLE_64B,
            CU_TENSOR_MAP_L2_PROMOTION_L2_128B, CU_TENSOR_MAP_FLOAT_OOB_FILL_NONE);
    }

    static bool attr_set = false;
    if (!attr_set) {
        cudaFuncSetAttribute(gat_kernel,
                             cudaFuncAttributeMaxDynamicSharedMemorySize,
                             SMEM_TOTAL);
        attr_set = true;
    }
    const int grid = N_ROWS / BM;   // 3125 (exact)
    gat_kernel<<<grid, THREADS, SMEM_TOTAL>>>(tmA, tmB, adj, out);
}